// round 5
// baseline (speedup 1.0000x reference)
#include <cuda_runtime.h>
#include <cstddef>

// ---------------------------------------------------------------------------
// DiffJPEG: per 8x8 block  ->  D X D^T  ->  round(x/Q)*Q  ->  D^T X' D
// Input/Output: (32, 3, 512, 512) float32, contiguous.
//
// Lane-pair split: even lane owns block rows 0-3, odd lane rows 7..4 (stored
// REVERSED: local j <-> global 7-j). The column-DCT even/odd butterfly then
// becomes a pointwise shfl.xor(1) + fmaf(sgn,...) in CONVERGED code; only the
// 4x4 const-matvec + quantize diverges (constants stay compile-time
// immediates in both paths, odd path uses negated O-matrix literals).
// ~32-float working set -> ~48 regs -> 5 CTAs/SM.
// ---------------------------------------------------------------------------

__host__ __device__ constexpr float COS9(int m) {
    constexpr float t[9] = {
        1.0f,
        0.9807852804032304f,
        0.9238795325112868f,
        0.8314696123025452f,
        0.7071067811865476f,
        0.5555702330196022f,
        0.3826834323650898f,
        0.1950903220161283f,
        0.0f
    };
    return t[m];
}

__host__ __device__ constexpr float cos16f(int m) {
    m &= 31;
    if (m <= 8)  return  COS9(m);
    if (m <= 16) return -COS9(16 - m);
    if (m <= 24) return -COS9(m - 16);
    return COS9(32 - m);
}

struct Mat8 { float v[8][8]; };
struct Mat4 { float v[4][4]; };

__host__ __device__ constexpr Mat8 makeD() {
    Mat8 d{};
    for (int i = 0; i < 8; i++)
        for (int j = 0; j < 8; j++)
            d.v[i][j] = (i == 0 ? 0.35355339059327373f : 0.5f) * cos16f((2 * j + 1) * i);
    return d;
}

// Even rows of D (i = 0,2,4,6), first 4 columns
__host__ __device__ constexpr Mat4 makeE() {
    Mat4 e{};
    constexpr Mat8 d = makeD();
    for (int k = 0; k < 4; k++)
        for (int j = 0; j < 4; j++)
            e.v[k][j] = d.v[2 * k][j];
    return e;
}
// Odd rows of D (i = 1,3,5,7), first 4 columns
__host__ __device__ constexpr Mat4 makeO() {
    Mat4 o{};
    constexpr Mat8 d = makeD();
    for (int k = 0; k < 4; k++)
        for (int j = 0; j < 4; j++)
            o.v[k][j] = d.v[2 * k + 1][j];
    return o;
}

// quality=50 -> scale=100 -> Q is exactly the integer luma table
__host__ __device__ constexpr Mat8 makeQ() {
    Mat8 q{};
    constexpr float t[8][8] = {
        {16, 11, 10, 16, 24, 40, 51, 61},
        {12, 12, 14, 19, 26, 58, 60, 55},
        {14, 13, 16, 24, 40, 57, 69, 56},
        {14, 17, 22, 29, 51, 87, 80, 62},
        {18, 22, 37, 56, 68, 109, 103, 77},
        {24, 35, 55, 64, 81, 104, 113, 92},
        {49, 64, 78, 87, 103, 121, 120, 101},
        {72, 92, 95, 98, 112, 100, 103, 99}};
    for (int i = 0; i < 8; i++)
        for (int j = 0; j < 8; j++)
            q.v[i][j] = t[i][j];
    return q;
}

__host__ __device__ constexpr Mat8 makeQinv() {
    Mat8 qi{};
    constexpr Mat8 q = makeQ();
    for (int i = 0; i < 8; i++)
        for (int j = 0; j < 8; j++)
            qi.v[i][j] = 1.0f / q.v[i][j];
    return qi;
}

constexpr int W            = 512;
constexpr int H            = 512;
constexpr int IMG_ELEMS    = H * W;       // 262144
constexpr float RMAGIC     = 12582912.0f; // 1.5 * 2^23 : round-half-even magic

// Forward 8-point DCT-II (orthonormal): out[i] = sum_j D[i][j] in[j]
__device__ __forceinline__ void dct8_fwd(const float in[8], float out[8]) {
    constexpr Mat4 E = makeE();
    constexpr Mat4 O = makeO();
    float s[4], d[4];
    #pragma unroll
    for (int j = 0; j < 4; j++) {
        s[j] = in[j] + in[7 - j];
        d[j] = in[j] - in[7 - j];
    }
    #pragma unroll
    for (int k = 0; k < 4; k++) {
        float se = s[0] * E.v[k][0];
        float so = d[0] * O.v[k][0];
        #pragma unroll
        for (int j = 1; j < 4; j++) {
            se += s[j] * E.v[k][j];
            so += d[j] * O.v[k][j];
        }
        out[2 * k]     = se;
        out[2 * k + 1] = so;
    }
}

// Inverse: out[j] = sum_i D[i][j] in[i]
__device__ __forceinline__ void dct8_inv(const float in[8], float out[8]) {
    constexpr Mat4 E = makeE();
    constexpr Mat4 O = makeO();
    #pragma unroll
    for (int j = 0; j < 4; j++) {
        float e = in[0] * E.v[0][j];
        float o = in[1] * O.v[0][j];
        #pragma unroll
        for (int k = 1; k < 4; k++) {
            e += in[2 * k]     * E.v[k][j];
            o += in[2 * k + 1] * O.v[k][j];
        }
        out[j]     = e + o;
        out[7 - j] = e - o;
    }
}

__global__ void __launch_bounds__(256, 5)
diffjpeg_kernel(const float* __restrict__ in, float* __restrict__ out, int nthreads) {
    constexpr Mat4 E4 = makeE();
    constexpr Mat4 O4 = makeO();
    constexpr Mat8 Q  = makeQ();
    constexpr Mat8 Qi = makeQinv();

    int t = blockIdx.x * 256 + threadIdx.x;
    if (t >= nthreads) return;   // never taken (exact grid), kept for safety

    int blk = t >> 1;
    int par = t & 1;             // 0: rows 0..3, 1: rows 7..4 (reversed local order)

    int img = blk >> 12;         // 4096 blocks per image
    int rem = blk & 4095;
    int br  = rem >> 6;
    int bc  = rem & 63;

    size_t base = (size_t)img * IMG_ELEMS + (size_t)br * 8 * W + (size_t)bc * 8;
    const float* src = in + base;
    float* dst = out + base;

    int   row0  = par ? 7 : 0;   // global row for local j=0
    int   rstep = par ? -1 : 1;
    float sgn   = par ? -1.0f : 1.0f;

    // U[j][c]: local j maps to global row (row0 + j*rstep)
    float U[4][8];

    // ---- Phase 1: load own 4 rows, row-transform in place ----
    #pragma unroll
    for (int j = 0; j < 4; j++) {
        int row = row0 + j * rstep;
        const float* p = src + (size_t)row * W;
        float4 a = *reinterpret_cast<const float4*>(p);
        float4 b = *reinterpret_cast<const float4*>(p + 4);
        float x[8] = {a.x, a.y, a.z, a.w, b.x, b.y, b.z, b.w};
        dct8_fwd(x, U[j]);       // U[j][c] = T[row][c],  T = X * D^T
    }

    // ---- Phase 2a (converged): column butterfly via lane-pair exchange ----
    // even lane: U[j] <- T[j] + T[7-j]        =  s_j   (column symmetric sum)
    // odd  lane: U[j] <- T[7-j] - T[j]        = -d_j   (negated diff)
    #pragma unroll
    for (int j = 0; j < 4; j++)
        #pragma unroll
        for (int c = 0; c < 8; c++) {
            float ex = __shfl_xor_sync(0xFFFFFFFFu, U[j][c], 1);
            U[j][c] = fmaf(sgn, ex, U[j][c]);
        }

    // ---- Phase 2b (divergent): 4x4 column matvec + quantize + inverse half ----
    if (par == 0) {
        // even DCT coefficients i = 2k; then e_j = sum_k E4[k][j] g[k]
        #pragma unroll
        for (int c = 0; c < 8; c++) {
            float f[4];
            #pragma unroll
            for (int k = 0; k < 4; k++) {
                float s = U[0][c] * E4.v[k][0];
                #pragma unroll
                for (int j = 1; j < 4; j++) s += U[j][c] * E4.v[k][j];
                // quantize with row 2k of Q
                float p  = s * Qi.v[2 * k][c];
                float r1 = __fadd_rn(p, RMAGIC);
                float r2 = __fadd_rn(r1, -RMAGIC);
                f[k] = r2 * Q.v[2 * k][c];
            }
            #pragma unroll
            for (int j = 0; j < 4; j++) {
                float s = f[0] * E4.v[0][j];
                #pragma unroll
                for (int k = 1; k < 4; k++) s += f[k] * E4.v[k][j];
                U[j][c] = s;     // e_j[c]
            }
        }
    } else {
        // odd DCT coefficients i = 2k+1 (sign folded into negated O4 literals);
        // then o_j = sum_k O4[k][j] g[k]
        #pragma unroll
        for (int c = 0; c < 8; c++) {
            float f[4];
            #pragma unroll
            for (int k = 0; k < 4; k++) {
                float s = U[0][c] * (-O4.v[k][0]);
                #pragma unroll
                for (int j = 1; j < 4; j++) s += U[j][c] * (-O4.v[k][j]);
                float p  = s * Qi.v[2 * k + 1][c];
                float r1 = __fadd_rn(p, RMAGIC);
                float r2 = __fadd_rn(r1, -RMAGIC);
                f[k] = r2 * Q.v[2 * k + 1][c];
            }
            #pragma unroll
            for (int j = 0; j < 4; j++) {
                float s = f[0] * O4.v[0][j];
                #pragma unroll
                for (int k = 1; k < 4; k++) s += f[k] * O4.v[k][j];
                U[j][c] = s;     // o_j[c]
            }
        }
    }

    // ---- Phase 2c (converged): recombine e/o across the lane pair ----
    // even lane: G[j]   = e_j + o_j = U + ex
    // odd  lane: G[7-j] = e_j - o_j = ex - U      (local j <-> global 7-j)
    #pragma unroll
    for (int j = 0; j < 4; j++)
        #pragma unroll
        for (int c = 0; c < 8; c++) {
            float ex = __shfl_xor_sync(0xFFFFFFFFu, U[j][c], 1);
            U[j][c] = fmaf(sgn, U[j][c], ex);
        }

    // ---- Phase 3: row inverse + store own rows ----
    #pragma unroll
    for (int j = 0; j < 4; j++) {
        float y[8];
        dct8_inv(U[j], y);
        int row = row0 + j * rstep;
        float* p = dst + (size_t)row * W;
        *reinterpret_cast<float4*>(p)     = make_float4(y[0], y[1], y[2], y[3]);
        *reinterpret_cast<float4*>(p + 4) = make_float4(y[4], y[5], y[6], y[7]);
    }
}

extern "C" void kernel_launch(void* const* d_in, const int* in_sizes, int n_in,
                              void* d_out, int out_size) {
    const float* in = (const float*)d_in[0];
    float* out = (float*)d_out;
    int nblocks  = in_sizes[0] / 64;   // 393216
    int nthreads = nblocks * 2;        // 786432, exact multiple of 256
    int grid = (nthreads + 255) / 256;
    diffjpeg_kernel<<<grid, 256>>>(in, out, nthreads);
}